// round 3
// baseline (speedup 1.0000x reference)
#include <cuda_runtime.h>

#define T_STEPS 200
#define IN 5
#define H 32
#define NB 4              // batch rows per warp
#define WARPS_PER_CTA 8
#define CTA 256

// Dual fp32 FMA via PTX fma.rn.f32x2 (sm_100+). Accumulates (i,f) and (g,o)
// gate pairs for one batch row with a scalar multiplier s broadcast to both halves.
__device__ __forceinline__ void ffma2x2(float& ai, float& af, float& ag, float& ao,
                                        float wx, float wy, float wz, float ww,
                                        float s) {
    asm("{\n\t"
        ".reg .b64 aif, ago, wif, wgo, ss;\n\t"
        "mov.b64 aif, {%0, %1};\n\t"
        "mov.b64 ago, {%2, %3};\n\t"
        "mov.b64 wif, {%4, %5};\n\t"
        "mov.b64 wgo, {%6, %7};\n\t"
        "mov.b64 ss,  {%8, %8};\n\t"
        "fma.rn.f32x2 aif, wif, ss, aif;\n\t"
        "fma.rn.f32x2 ago, wgo, ss, ago;\n\t"
        "mov.b64 {%0, %1}, aif;\n\t"
        "mov.b64 {%2, %3}, ago;\n\t"
        "}"
        : "+f"(ai), "+f"(af), "+f"(ag), "+f"(ao)
        : "f"(wx), "f"(wy), "f"(wz), "f"(ww), "f"(s));
}

// Fast-but-accurate activations: EX2+RCP based, abs err ~1e-6 (vs 1e-3 budget).
__device__ __forceinline__ float sigm(float x) {
    return __fdividef(1.0f, 1.0f + __expf(-x));
}
__device__ __forceinline__ float tanh_f(float x) {
    return 2.0f * sigm(2.0f * x) - 1.0f;
}

__global__ void __launch_bounds__(CTA, 3)
lstm_kernel(const float* __restrict__ x,
            const float* __restrict__ W_ih, const float* __restrict__ W_hh,
            const float* __restrict__ b_ih, const float* __restrict__ b_hh,
            const float* __restrict__ W_fc, const float* __restrict__ b_fc,
            float* __restrict__ out, int B) {
    // Weight layout: Wh4[k][j] = (W_hh[j][k], W_hh[32+j][k], W_hh[64+j][k], W_hh[96+j][k])
    // -> lane j does one LDS.128 per k covering all 4 of its gates. Conflict-free.
    __shared__ float4 Wx4[IN][H];
    __shared__ float4 Wh4[H][H];
    __shared__ float4 hbuf[WARPS_PER_CTA][H];   // hbuf[w][k] = h_k of the 4 batch rows

    const int tid = threadIdx.x;
    for (int idx = tid; idx < H * H; idx += CTA) {
        int k = idx >> 5, j = idx & 31;
        Wh4[k][j] = make_float4(W_hh[j * H + k],
                                W_hh[(H + j) * H + k],
                                W_hh[(2 * H + j) * H + k],
                                W_hh[(3 * H + j) * H + k]);
    }
    for (int idx = tid; idx < IN * H; idx += CTA) {
        int k = idx >> 5, j = idx & 31;
        Wx4[k][j] = make_float4(W_ih[j * IN + k],
                                W_ih[(H + j) * IN + k],
                                W_ih[(2 * H + j) * IN + k],
                                W_ih[(3 * H + j) * IN + k]);
    }
    __syncthreads();

    const int w    = tid >> 5;
    const int lane = tid & 31;
    const int b0   = (blockIdx.x * WARPS_PER_CTA + w) * NB;
    if (b0 >= B) return;   // warp-uniform

    const int j = lane;
    const float bias_i = b_ih[j]         + b_hh[j];
    const float bias_f = b_ih[H + j]     + b_hh[H + j];
    const float bias_g = b_ih[2 * H + j] + b_hh[2 * H + j];
    const float bias_o = b_ih[3 * H + j] + b_hh[3 * H + j];

    // Clamp row indices so a ragged tail never reads OOB (B=16384 -> never ragged).
    const int bA = b0;
    const int bB = min(b0 + 1, B - 1);
    const int bC = min(b0 + 2, B - 1);
    const int bD = min(b0 + 3, B - 1);
    const float* x0 = x + (size_t)bA * (T_STEPS * IN);
    const float* x1 = x + (size_t)bB * (T_STEPS * IN);
    const float* x2 = x + (size_t)bC * (T_STEPS * IN);
    const float* x3 = x + (size_t)bD * (T_STEPS * IN);

    float h0 = 0.f, h1 = 0.f, h2 = 0.f, h3 = 0.f;
    float c0 = 0.f, c1 = 0.f, c2 = 0.f, c3 = 0.f;

    for (int t = 0; t < T_STEPS; ++t) {
        float ai0 = bias_i, af0 = bias_f, ag0 = bias_g, ao0 = bias_o;
        float ai1 = bias_i, af1 = bias_f, ag1 = bias_g, ao1 = bias_o;
        float ai2 = bias_i, af2 = bias_f, ag2 = bias_g, ao2 = bias_o;
        float ai3 = bias_i, af3 = bias_f, ag3 = bias_g, ao3 = bias_o;

        const int t5 = t * IN;
        // Input projection (inline: avoids 3.3 GB x_proj round trip)
        #pragma unroll
        for (int k = 0; k < IN; ++k) {
            float4 wv = Wx4[k][j];
            float s0 = __ldg(x0 + t5 + k);
            float s1 = __ldg(x1 + t5 + k);
            float s2 = __ldg(x2 + t5 + k);
            float s3 = __ldg(x3 + t5 + k);
            ffma2x2(ai0, af0, ag0, ao0, wv.x, wv.y, wv.z, wv.w, s0);
            ffma2x2(ai1, af1, ag1, ao1, wv.x, wv.y, wv.z, wv.w, s1);
            ffma2x2(ai2, af2, ag2, ao2, wv.x, wv.y, wv.z, wv.w, s2);
            ffma2x2(ai3, af3, ag3, ao3, wv.x, wv.y, wv.z, wv.w, s3);
        }

        // Publish h of the 4 rows; lane j writes index j (stride-16B, conflict-free).
        __syncwarp();
        hbuf[w][j] = make_float4(h0, h1, h2, h3);
        __syncwarp();

        // Recurrent matvec: broadcast LDS.128 of (h0..h3)[k] + weight LDS.128,
        // 8 FFMA2 per k serving 4 batch rows.
        #pragma unroll
        for (int k = 0; k < H; ++k) {
            float4 wv = Wh4[k][j];
            float4 hk = hbuf[w][k];
            ffma2x2(ai0, af0, ag0, ao0, wv.x, wv.y, wv.z, wv.w, hk.x);
            ffma2x2(ai1, af1, ag1, ao1, wv.x, wv.y, wv.z, wv.w, hk.y);
            ffma2x2(ai2, af2, ag2, ao2, wv.x, wv.y, wv.z, wv.w, hk.z);
            ffma2x2(ai3, af3, ag3, ao3, wv.x, wv.y, wv.z, wv.w, hk.w);
        }

        // Gate activations + state update (torch order i,f,g,o)
        {
            float i_ = sigm(ai0), f_ = sigm(af0), g_ = tanh_f(ag0), o_ = sigm(ao0);
            c0 = f_ * c0 + i_ * g_;  h0 = o_ * tanh_f(c0);
        }
        {
            float i_ = sigm(ai1), f_ = sigm(af1), g_ = tanh_f(ag1), o_ = sigm(ao1);
            c1 = f_ * c1 + i_ * g_;  h1 = o_ * tanh_f(c1);
        }
        {
            float i_ = sigm(ai2), f_ = sigm(af2), g_ = tanh_f(ag2), o_ = sigm(ao2);
            c2 = f_ * c2 + i_ * g_;  h2 = o_ * tanh_f(c2);
        }
        {
            float i_ = sigm(ai3), f_ = sigm(af3), g_ = tanh_f(ag3), o_ = sigm(ao3);
            c3 = f_ * c3 + i_ * g_;  h3 = o_ * tanh_f(c3);
        }
    }

    // Final FC: out[b, o] = h . W_fc[o, :] + b_fc[o]; butterfly reduce over lanes.
    float wf0 = W_fc[j];
    float wf1 = W_fc[H + j];
    float s00 = h0 * wf0, s01 = h0 * wf1;
    float s10 = h1 * wf0, s11 = h1 * wf1;
    float s20 = h2 * wf0, s21 = h2 * wf1;
    float s30 = h3 * wf0, s31 = h3 * wf1;
    #pragma unroll
    for (int off = 16; off; off >>= 1) {
        s00 += __shfl_xor_sync(0xFFFFFFFFu, s00, off);
        s01 += __shfl_xor_sync(0xFFFFFFFFu, s01, off);
        s10 += __shfl_xor_sync(0xFFFFFFFFu, s10, off);
        s11 += __shfl_xor_sync(0xFFFFFFFFu, s11, off);
        s20 += __shfl_xor_sync(0xFFFFFFFFu, s20, off);
        s21 += __shfl_xor_sync(0xFFFFFFFFu, s21, off);
        s30 += __shfl_xor_sync(0xFFFFFFFFu, s30, off);
        s31 += __shfl_xor_sync(0xFFFFFFFFu, s31, off);
    }
    if (lane == 0) {
        float bf0 = b_fc[0], bf1 = b_fc[1];
        out[(size_t)b0 * 2 + 0] = s00 + bf0;
        out[(size_t)b0 * 2 + 1] = s01 + bf1;
        if (b0 + 1 < B) { out[(size_t)(b0 + 1) * 2 + 0] = s10 + bf0;
                          out[(size_t)(b0 + 1) * 2 + 1] = s11 + bf1; }
        if (b0 + 2 < B) { out[(size_t)(b0 + 2) * 2 + 0] = s20 + bf0;
                          out[(size_t)(b0 + 2) * 2 + 1] = s21 + bf1; }
        if (b0 + 3 < B) { out[(size_t)(b0 + 3) * 2 + 0] = s30 + bf0;
                          out[(size_t)(b0 + 3) * 2 + 1] = s31 + bf1; }
    }
}

extern "C" void kernel_launch(void* const* d_in, const int* in_sizes, int n_in,
                              void* d_out, int out_size) {
    const float* x    = (const float*)d_in[0];
    const float* W_ih = (const float*)d_in[1];
    const float* W_hh = (const float*)d_in[2];
    const float* b_ih = (const float*)d_in[3];
    const float* b_hh = (const float*)d_in[4];
    const float* W_fc = (const float*)d_in[5];
    const float* b_fc = (const float*)d_in[6];
    float* out = (float*)d_out;

    const int B = in_sizes[0] / (T_STEPS * IN);
    const int groups = (B + NB - 1) / NB;                       // warps needed
    const int ctas   = (groups + WARPS_PER_CTA - 1) / WARPS_PER_CTA;
    lstm_kernel<<<ctas, CTA>>>(x, W_ih, W_hh, b_ih, b_hh, W_fc, b_fc, out, B);
}

// round 7
// speedup vs baseline: 1.0208x; 1.0208x over previous
#include <cuda_runtime.h>

#define T_STEPS 200
#define IN 5
#define H 32
#define NB 8               // batch rows per warp
#define WARPS_PER_CTA 2
#define CTA 64
#define ROWS_PER_CTA (NB * WARPS_PER_CTA)   // 16

// Pre-transposed weights (built once by prep_kernel; static device arrays, no alloc).
__device__ float4 g_Wx4[IN][H];
__device__ float4 g_Wh4[H][H];
__device__ float  g_bias[4 * H];

// Dual fp32 FMA via PTX fma.rn.f32x2 (sm_100+): 4 gate-MACs in 2 FMA-pipe slots.
__device__ __forceinline__ void ffma2x2(float& ai, float& af, float& ag, float& ao,
                                        float wx, float wy, float wz, float ww,
                                        float s) {
    asm("{\n\t"
        ".reg .b64 aif, ago, wif, wgo, ss;\n\t"
        "mov.b64 aif, {%0, %1};\n\t"
        "mov.b64 ago, {%2, %3};\n\t"
        "mov.b64 wif, {%4, %5};\n\t"
        "mov.b64 wgo, {%6, %7};\n\t"
        "mov.b64 ss,  {%8, %8};\n\t"
        "fma.rn.f32x2 aif, wif, ss, aif;\n\t"
        "fma.rn.f32x2 ago, wgo, ss, ago;\n\t"
        "mov.b64 {%0, %1}, aif;\n\t"
        "mov.b64 {%2, %3}, ago;\n\t"
        "}"
        : "+f"(ai), "+f"(af), "+f"(ag), "+f"(ao)
        : "f"(wx), "f"(wy), "f"(wz), "f"(ww), "f"(s));
}

// EX2+RCP activations, abs err ~1e-6 (proven rel_err 2e-7 end-to-end).
__device__ __forceinline__ float sigm(float x) {
    return __fdividef(1.0f, 1.0f + __expf(-x));
}
__device__ __forceinline__ float tanh_f(float x) {
    return 2.0f * sigm(2.0f * x) - 1.0f;
}

__global__ void prep_kernel(const float* __restrict__ W_ih,
                            const float* __restrict__ W_hh,
                            const float* __restrict__ b_ih,
                            const float* __restrict__ b_hh) {
    const int tid = threadIdx.x;   // 128 threads
    for (int idx = tid; idx < H * H; idx += 128) {
        int k = idx >> 5, j = idx & 31;
        g_Wh4[k][j] = make_float4(W_hh[j * H + k],
                                  W_hh[(H + j) * H + k],
                                  W_hh[(2 * H + j) * H + k],
                                  W_hh[(3 * H + j) * H + k]);
    }
    for (int idx = tid; idx < IN * H; idx += 128) {
        int k = idx / H, j = idx % H;
        g_Wx4[k][j] = make_float4(W_ih[j * IN + k],
                                  W_ih[(H + j) * IN + k],
                                  W_ih[(2 * H + j) * IN + k],
                                  W_ih[(3 * H + j) * IN + k]);
    }
    if (tid < 4 * H) g_bias[tid] = b_ih[tid] + b_hh[tid];
}

__global__ void __launch_bounds__(CTA, 7)
lstm_kernel(const float* __restrict__ x,
            const float* __restrict__ W_fc, const float* __restrict__ b_fc,
            float* __restrict__ out, int B) {
    __shared__ float4 Wx4[IN][H];
    __shared__ float4 Wh4[H][H];
    __shared__ float4 hbufA[WARPS_PER_CTA][H];   // h of rows 0-3 per k
    __shared__ float4 hbufB[WARPS_PER_CTA][H];   // h of rows 4-7 per k

    const int tid = threadIdx.x;
    // Coalesced smem fill from pre-transposed globals.
    {
        const float4* src = &g_Wh4[0][0];
        float4* dst = &Wh4[0][0];
        for (int i = tid; i < H * H; i += CTA) dst[i] = src[i];
        const float4* src2 = &g_Wx4[0][0];
        float4* dst2 = &Wx4[0][0];
        for (int i = tid; i < IN * H; i += CTA) dst2[i] = src2[i];
    }
    __syncthreads();

    const int w    = tid >> 5;
    const int lane = tid & 31;
    const int b0   = (blockIdx.x * WARPS_PER_CTA + w) * NB;
    if (b0 >= B) return;   // warp-uniform; no CTA-wide syncs after this point

    const int j = lane;
    const float bias_i = g_bias[j];
    const float bias_f = g_bias[H + j];
    const float bias_g = g_bias[2 * H + j];
    const float bias_o = g_bias[3 * H + j];

    const float* xp[NB];
    #pragma unroll
    for (int r = 0; r < NB; ++r) {
        int br = min(b0 + r, B - 1);
        xp[r] = x + (size_t)br * (T_STEPS * IN);
    }

    float h[NB], c[NB];
    #pragma unroll
    for (int r = 0; r < NB; ++r) { h[r] = 0.f; c[r] = 0.f; }

    for (int t = 0; t < T_STEPS; ++t) {
        float ai[NB], af[NB], ag[NB], ao[NB];
        #pragma unroll
        for (int r = 0; r < NB; ++r) {
            ai[r] = bias_i; af[r] = bias_f; ag[r] = bias_g; ao[r] = bias_o;
        }

        const int t5 = t * IN;
        // Input projection inline (x stays in L1; avoids any x_proj round trip).
        #pragma unroll
        for (int k = 0; k < IN; ++k) {
            float4 wv = Wx4[k][j];
            #pragma unroll
            for (int r = 0; r < NB; ++r) {
                float s = __ldg(xp[r] + t5 + k);
                ffma2x2(ai[r], af[r], ag[r], ao[r], wv.x, wv.y, wv.z, wv.w, s);
            }
        }

        // Publish h (lane j writes slot j: conflict-free stride-16B stores).
        __syncwarp();
        hbufA[w][j] = make_float4(h[0], h[1], h[2], h[3]);
        hbufB[w][j] = make_float4(h[4], h[5], h[6], h[7]);
        __syncwarp();

        // Recurrent matvec: 1 weight LDS.128 (4 wavefronts) + 2 broadcast loads
        // serve 8 batch rows -> 0.75 L1 wavefronts per row per k.
        #pragma unroll
        for (int k = 0; k < H; ++k) {
            float4 wv = Wh4[k][j];
            float4 ha = hbufA[w][k];
            float4 hb = hbufB[w][k];
            ffma2x2(ai[0], af[0], ag[0], ao[0], wv.x, wv.y, wv.z, wv.w, ha.x);
            ffma2x2(ai[1], af[1], ag[1], ao[1], wv.x, wv.y, wv.z, wv.w, ha.y);
            ffma2x2(ai[2], af[2], ag[2], ao[2], wv.x, wv.y, wv.z, wv.w, ha.z);
            ffma2x2(ai[3], af[3], ag[3], ao[3], wv.x, wv.y, wv.z, wv.w, ha.w);
            ffma2x2(ai[4], af[4], ag[4], ao[4], wv.x, wv.y, wv.z, wv.w, hb.x);
            ffma2x2(ai[5], af[5], ag[5], ao[5], wv.x, wv.y, wv.z, wv.w, hb.y);
            ffma2x2(ai[6], af[6], ag[6], ao[6], wv.x, wv.y, wv.z, wv.w, hb.z);
            ffma2x2(ai[7], af[7], ag[7], ao[7], wv.x, wv.y, wv.z, wv.w, hb.w);
        }

        // Gate activations + state update (torch order i,f,g,o)
        #pragma unroll
        for (int r = 0; r < NB; ++r) {
            float i_ = sigm(ai[r]);
            float f_ = sigm(af[r]);
            float g_ = tanh_f(ag[r]);
            float o_ = sigm(ao[r]);
            c[r] = f_ * c[r] + i_ * g_;
            h[r] = o_ * tanh_f(c[r]);
        }
    }

    // Final FC: out[b, o] = h . W_fc[o, :] + b_fc[o]; butterfly reduce.
    float wf0 = W_fc[j];
    float wf1 = W_fc[H + j];
    float s0[NB], s1[NB];
    #pragma unroll
    for (int r = 0; r < NB; ++r) { s0[r] = h[r] * wf0; s1[r] = h[r] * wf1; }
    #pragma unroll
    for (int off = 16; off; off >>= 1) {
        #pragma unroll
        for (int r = 0; r < NB; ++r) {
            s0[r] += __shfl_xor_sync(0xFFFFFFFFu, s0[r], off);
            s1[r] += __shfl_xor_sync(0xFFFFFFFFu, s1[r], off);
        }
    }
    if (lane == 0) {
        float bf0 = b_fc[0], bf1 = b_fc[1];
        #pragma unroll
        for (int r = 0; r < NB; ++r) {
            if (b0 + r < B) {
                out[(size_t)(b0 + r) * 2 + 0] = s0[r] + bf0;
                out[(size_t)(b0 + r) * 2 + 1] = s1[r] + bf1;
            }
        }
    }
}

extern "C" void kernel_launch(void* const* d_in, const int* in_sizes, int n_in,
                              void* d_out, int out_size) {
    const float* x    = (const float*)d_in[0];
    const float* W_ih = (const float*)d_in[1];
    const float* W_hh = (const float*)d_in[2];
    const float* b_ih = (const float*)d_in[3];
    const float* b_hh = (const float*)d_in[4];
    const float* W_fc = (const float*)d_in[5];
    const float* b_fc = (const float*)d_in[6];
    float* out = (float*)d_out;

    const int B = in_sizes[0] / (T_STEPS * IN);
    prep_kernel<<<1, 128>>>(W_ih, W_hh, b_ih, b_hh);
    const int ctas = (B + ROWS_PER_CTA - 1) / ROWS_PER_CTA;   // 1024 for B=16384
    lstm_kernel<<<ctas, CTA>>>(x, W_fc, b_fc, out, B);
}